// round 10
// baseline (speedup 1.0000x reference)
#include <cuda_runtime.h>
#include <cuda_fp16.h>
#include <cstdint>

// Fully-fused MLP 64->128->128->128->128->64, ReLU on all but last (mma.sync).
// 12 warps x 32 rows/warp, j-pair accumulator tiles, K-parity-SPLIT dual
// accumulators (even/odd s-steps) to double independent HMMA chains per warp
// (8 instead of 4) -> hide long HMMA RAW latency. Ping-pong A-frag buffers,
// weights in padded SMEM, warps fully independent, no syncs in the loop.

#define NROWS      (1 << 20)
#define THREADS    384
#define WARPS      12
#define M_PER_WARP 32
#define WTILES     (NROWS / M_PER_WARP)      // 32768 warp-tiles

// shared strides in halves (conflict-free B-frag loads: 4g+t distinct banks)
#define SA   136
#define SW0  72

#define OFF_W0  0
#define OFF_W1  (OFF_W0 + 128 * SW0)
#define OFF_W2  (OFF_W1 + 128 * SA)
#define OFF_W3  (OFF_W2 + 128 * SA)
#define OFF_W4  (OFF_W3 + 128 * SA)
#define HALVES  (OFF_W4 + 64 * SA)               // 70144 halves
#define BIAS_OFF   (HALVES * 2)                  // 140288 B
#define SMEM_BYTES (BIAS_OFF + 576 * 4)          // 142592 B

__device__ __forceinline__ void mma16816(float c[4], const uint32_t a[4], const uint32_t b[2]) {
    asm volatile(
        "mma.sync.aligned.m16n8k16.row.col.f32.f16.f16.f32 "
        "{%0,%1,%2,%3}, {%4,%5,%6,%7}, {%8,%9}, {%0,%1,%2,%3};\n"
        : "+f"(c[0]), "+f"(c[1]), "+f"(c[2]), "+f"(c[3])
        : "r"(a[0]), "r"(a[1]), "r"(a[2]), "r"(a[3]), "r"(b[0]), "r"(b[1]));
}

__device__ __forceinline__ uint32_t packh2(float x, float y) {
    half2 h = __floats2half2_rn(x, y);
    return *(uint32_t*)&h;
}
__device__ __forceinline__ uint32_t relu_pack(float x, float y) {
    half2 h = __floats2half2_rn(fmaxf(x, 0.f), fmaxf(y, 0.f));
    return *(uint32_t*)&h;
}

// One j-pair (16 output cols) of a layer, K-parity-split accumulators.
// Reads A-frags src (KS k-blocks), writes packed fp16 A-frag k-block p of dst.
template <int KS>
__device__ __forceinline__ void layer_pair(
    const uint32_t* __restrict__ W32, int sWh,
    const float* __restrict__ bias,
    const uint32_t src[2][8][4], uint32_t dst[2][8][4],
    int p, int g, int t)
{
    float ae[2][2][4];   // even s-steps (bias preloaded)
    float ao[2][2][4];   // odd  s-steps (zero)
#pragma unroll
    for (int jj = 0; jj < 2; jj++) {
        const float2 bb = *(const float2*)&bias[(p * 2 + jj) * 8 + t * 2];
#pragma unroll
        for (int mt = 0; mt < 2; mt++) {
            ae[mt][jj][0] = bb.x; ae[mt][jj][1] = bb.y;
            ae[mt][jj][2] = bb.x; ae[mt][jj][3] = bb.y;
            ao[mt][jj][0] = 0.f;  ao[mt][jj][1] = 0.f;
            ao[mt][jj][2] = 0.f;  ao[mt][jj][3] = 0.f;
        }
    }
#pragma unroll
    for (int s = 0; s < KS; s++) {
        const int k0 = s * 16 + t * 2;
#pragma unroll
        for (int jj = 0; jj < 2; jj++) {
            const int n = (p * 2 + jj) * 8 + g;
            uint32_t b[2];
            b[0] = W32[(n * sWh + k0) >> 1];
            b[1] = W32[(n * sWh + k0 + 8) >> 1];
            if (s & 1) {
                mma16816(ao[0][jj], src[0][s], b);
                mma16816(ao[1][jj], src[1][s], b);
            } else {
                mma16816(ae[0][jj], src[0][s], b);
                mma16816(ae[1][jj], src[1][s], b);
            }
        }
    }
#pragma unroll
    for (int mt = 0; mt < 2; mt++) {
        dst[mt][p][0] = relu_pack(ae[mt][0][0] + ao[mt][0][0], ae[mt][0][1] + ao[mt][0][1]);
        dst[mt][p][1] = relu_pack(ae[mt][0][2] + ao[mt][0][2], ae[mt][0][3] + ao[mt][0][3]);
        dst[mt][p][2] = relu_pack(ae[mt][1][0] + ao[mt][1][0], ae[mt][1][1] + ao[mt][1][1]);
        dst[mt][p][3] = relu_pack(ae[mt][1][2] + ao[mt][1][2], ae[mt][1][3] + ao[mt][1][3]);
    }
}

__global__ __launch_bounds__(THREADS, 1)
void FullyFusedMLP_kernel(
    const float* __restrict__ x,
    const float* __restrict__ w_in,  const float* __restrict__ b_in,
    const float* __restrict__ w_hid, const float* __restrict__ b_hid,
    const float* __restrict__ w_out, const float* __restrict__ b_out,
    float* __restrict__ out)
{
    extern __shared__ char smem_raw[];
    half* sh = (half*)smem_raw;
    half* w0 = sh + OFF_W0;
    half* w1 = sh + OFF_W1;
    half* w2 = sh + OFF_W2;
    half* w3 = sh + OFF_W3;
    half* w4 = sh + OFF_W4;
    float* biass = (float*)(smem_raw + BIAS_OFF);
    // bias layout: [0:128) b_in, [128:512) b_hid (3x128), [512:576) b_out

    const int tid = threadIdx.x;

    // ---- stage weights/biases to shared once per CTA ----
    for (int i = tid; i < 128 * 64; i += THREADS) {
        int n = i >> 6, k = i & 63;
        w0[n * SW0 + k] = __float2half(w_in[i]);
    }
    {
        half* wl[3] = {w1, w2, w3};
#pragma unroll
        for (int l = 0; l < 3; l++) {
            const float* src = w_hid + l * 128 * 128;
            half* dst = wl[l];
            for (int i = tid; i < 128 * 128; i += THREADS) {
                int n = i >> 7, k = i & 127;
                dst[n * SA + k] = __float2half(src[i]);
            }
        }
    }
    for (int i = tid; i < 64 * 128; i += THREADS) {
        int n = i >> 7, k = i & 127;
        w4[n * SA + k] = __float2half(w_out[i]);
    }
    for (int i = tid; i < 128; i += THREADS)     biass[i]       = b_in[i];
    for (int i = tid; i < 3 * 128; i += THREADS) biass[128 + i] = b_hid[i];
    for (int i = tid; i < 64; i += THREADS)      biass[512 + i] = b_out[i];
    __syncthreads();   // the ONLY sync

    const int warp = tid >> 5, lane = tid & 31;
    const int g = lane >> 2, t = lane & 3;

    const uint32_t* w0_32 = (const uint32_t*)w0;
    const uint32_t* w1_32 = (const uint32_t*)w1;
    const uint32_t* w2_32 = (const uint32_t*)w2;
    const uint32_t* w3_32 = (const uint32_t*)w3;
    const uint32_t* w4_32 = (const uint32_t*)w4;

    uint32_t af[2][8][4];    // ping
    uint32_t bf[2][8][4];    // pong

    const int gwarp   = blockIdx.x * WARPS + warp;
    const int wstride = gridDim.x * WARPS;

    for (int wt = gwarp; wt < WTILES; wt += wstride) {
        const size_t row0 = (size_t)wt * M_PER_WARP;

        // ---- x: gmem -> af A-frags (fp32 -> fp16), k-blocks 0..3 ----
        {
            const float* xp = x + row0 * 64;
#pragma unroll
            for (int mt = 0; mt < 2; mt++) {
                const int rA = mt * 16 + g;
#pragma unroll
                for (int s = 0; s < 4; s++) {
                    const int c0 = s * 16 + t * 2;
                    float2 v0 = *(const float2*)&xp[rA * 64 + c0];
                    float2 v1 = *(const float2*)&xp[(rA + 8) * 64 + c0];
                    float2 v2 = *(const float2*)&xp[rA * 64 + c0 + 8];
                    float2 v3 = *(const float2*)&xp[(rA + 8) * 64 + c0 + 8];
                    af[mt][s][0] = packh2(v0.x, v0.y);
                    af[mt][s][1] = packh2(v1.x, v1.y);
                    af[mt][s][2] = packh2(v2.x, v2.y);
                    af[mt][s][3] = packh2(v3.x, v3.y);
                }
            }
        }

        // ---- layer 0: K=64, af -> bf ----
#pragma unroll
        for (int p = 0; p < 8; p++)
            layer_pair<4>(w0_32, SW0, biass, af, bf, p, g, t);

        // ---- layer 1: K=128, bf -> af ----
#pragma unroll
        for (int p = 0; p < 8; p++)
            layer_pair<8>(w1_32, SA, biass + 128, bf, af, p, g, t);

        // ---- layer 2: af -> bf ----
#pragma unroll
        for (int p = 0; p < 8; p++)
            layer_pair<8>(w2_32, SA, biass + 256, af, bf, p, g, t);

        // ---- layer 3: bf -> af ----
#pragma unroll
        for (int p = 0; p < 8; p++)
            layer_pair<8>(w3_32, SA, biass + 384, bf, af, p, g, t);

        // ---- layer 4: K=128 -> N=64, no activation, store fp32 ----
        const float* bo = biass + 512;
#pragma unroll
        for (int p = 0; p < 4; p++) {
            float ae[2][2][4], ao[2][2][4];
#pragma unroll
            for (int jj = 0; jj < 2; jj++) {
                const float2 bb = *(const float2*)&bo[(p * 2 + jj) * 8 + t * 2];
#pragma unroll
                for (int mt = 0; mt < 2; mt++) {
                    ae[mt][jj][0] = bb.x; ae[mt][jj][1] = bb.y;
                    ae[mt][jj][2] = bb.x; ae[mt][jj][3] = bb.y;
                    ao[mt][jj][0] = 0.f;  ao[mt][jj][1] = 0.f;
                    ao[mt][jj][2] = 0.f;  ao[mt][jj][3] = 0.f;
                }
            }
#pragma unroll
            for (int s = 0; s < 8; s++) {
                const int k0 = s * 16 + t * 2;
#pragma unroll
                for (int jj = 0; jj < 2; jj++) {
                    const int n = (p * 2 + jj) * 8 + g;
                    uint32_t b[2];
                    b[0] = w4_32[(n * SA + k0) >> 1];
                    b[1] = w4_32[(n * SA + k0 + 8) >> 1];
                    if (s & 1) {
                        mma16816(ao[0][jj], af[0][s], b);
                        mma16816(ao[1][jj], af[1][s], b);
                    } else {
                        mma16816(ae[0][jj], af[0][s], b);
                        mma16816(ae[1][jj], af[1][s], b);
                    }
                }
            }
#pragma unroll
            for (int mt = 0; mt < 2; mt++) {
                const size_t r = row0 + mt * 16 + g;
#pragma unroll
                for (int jj = 0; jj < 2; jj++) {
                    const int n = (p * 2 + jj) * 8 + t * 2;
                    *(float2*)&out[r * 64 + n] =
                        make_float2(ae[mt][jj][0] + ao[mt][jj][0], ae[mt][jj][1] + ao[mt][jj][1]);
                    *(float2*)&out[(r + 8) * 64 + n] =
                        make_float2(ae[mt][jj][2] + ao[mt][jj][2], ae[mt][jj][3] + ao[mt][jj][3]);
                }
            }
        }
    }
}

extern "C" void kernel_launch(void* const* d_in, const int* in_sizes, int n_in,
                              void* d_out, int out_size) {
    const float* x     = (const float*)d_in[0];
    const float* w_in  = (const float*)d_in[1];
    const float* b_in  = (const float*)d_in[2];
    const float* w_hid = (const float*)d_in[3];
    const float* b_hid = (const float*)d_in[4];
    const float* w_out = (const float*)d_in[5];
    const float* b_out = (const float*)d_in[6];
    float* out = (float*)d_out;

    int nsm = 148;
    cudaDeviceGetAttribute(&nsm, cudaDevAttrMultiProcessorCount, 0);
    if (nsm < 1) nsm = 148;
    int grid = nsm;

    cudaFuncSetAttribute(FullyFusedMLP_kernel,
                         cudaFuncAttributeMaxDynamicSharedMemorySize, SMEM_BYTES);
    FullyFusedMLP_kernel<<<grid, THREADS, SMEM_BYTES>>>(
        x, w_in, b_in, w_hid, b_hid, w_out, b_out, out);
}

// round 11
// speedup vs baseline: 1.2609x; 1.2609x over previous
#include <cuda_runtime.h>
#include <cuda_fp16.h>
#include <cstdint>

// Fully-fused MLP 64->128->128->128->128->64, ReLU on all but last (mma.sync).
// 12 warps x 32 rows/warp, j-pair accumulators, ldmatrix.x4 B-fragment loads
// (1 LDSM per 4 HMMAs), ping-pong A-frag registers, weights in padded SMEM,
// warps fully independent, no syncs in the main loop.

#define NROWS      (1 << 20)
#define THREADS    384
#define WARPS      12
#define M_PER_WARP 32
#define WTILES     (NROWS / M_PER_WARP)      // 32768 warp-tiles

// shared strides in halves; both strides are ≡4 mod 32 words -> conflict-free
#define SA   136
#define SW0  72

#define OFF_W0  0
#define OFF_W1  (OFF_W0 + 128 * SW0)
#define OFF_W2  (OFF_W1 + 128 * SA)
#define OFF_W3  (OFF_W2 + 128 * SA)
#define OFF_W4  (OFF_W3 + 128 * SA)
#define HALVES  (OFF_W4 + 64 * SA)               // 70144 halves
#define BIAS_OFF   (HALVES * 2)                  // 140288 B
#define SMEM_BYTES (BIAS_OFF + 576 * 4)          // 142592 B

__device__ __forceinline__ void mma16816(float c[4], const uint32_t a[4],
                                         uint32_t b0, uint32_t b1) {
    asm volatile(
        "mma.sync.aligned.m16n8k16.row.col.f32.f16.f16.f32 "
        "{%0,%1,%2,%3}, {%4,%5,%6,%7}, {%8,%9}, {%0,%1,%2,%3};\n"
        : "+f"(c[0]), "+f"(c[1]), "+f"(c[2]), "+f"(c[3])
        : "r"(a[0]), "r"(a[1]), "r"(a[2]), "r"(a[3]), "r"(b0), "r"(b1));
}

__device__ __forceinline__ void ldsm4(uint32_t& r0, uint32_t& r1, uint32_t& r2, uint32_t& r3,
                                      uint32_t addr) {
    asm volatile("ldmatrix.sync.aligned.m8n8.x4.shared.b16 {%0,%1,%2,%3}, [%4];"
                 : "=r"(r0), "=r"(r1), "=r"(r2), "=r"(r3) : "r"(addr));
}

__device__ __forceinline__ uint32_t smem_u32(const void* p) {
    uint32_t a;
    asm("{ .reg .u64 t; cvta.to.shared.u64 t, %1; cvt.u32.u64 %0, t; }" : "=r"(a) : "l"(p));
    return a;
}

__device__ __forceinline__ uint32_t packh2(float x, float y) {
    half2 h = __floats2half2_rn(x, y);
    return *(uint32_t*)&h;
}
__device__ __forceinline__ uint32_t relu_pack(float x, float y) {
    half2 h = __floats2half2_rn(fmaxf(x, 0.f), fmaxf(y, 0.f));
    return *(uint32_t*)&h;
}

// One j-pair (16 output cols). wb = per-lane LDSM base byte-address for this
// layer's W; addr(p,s) = wb + (p*16*sWh + s*16)*2.
template <int KS>
__device__ __forceinline__ void layer_pair(
    uint32_t wb, int sWh,
    const float* __restrict__ bias,
    const uint32_t src[2][8][4], uint32_t dst[2][8][4],
    int p, int t)
{
    float acc[2][2][4];
#pragma unroll
    for (int jj = 0; jj < 2; jj++) {
        const float2 bb = *(const float2*)&bias[(p * 2 + jj) * 8 + t * 2];
#pragma unroll
        for (int mt = 0; mt < 2; mt++) {
            acc[mt][jj][0] = bb.x; acc[mt][jj][1] = bb.y;
            acc[mt][jj][2] = bb.x; acc[mt][jj][3] = bb.y;
        }
    }
    const uint32_t pbase = wb + (uint32_t)(p * 16 * sWh) * 2u;
#pragma unroll
    for (int s = 0; s < KS; s++) {
        uint32_t r0, r1, r2, r3;
        ldsm4(r0, r1, r2, r3, pbase + (uint32_t)(s * 32));
        mma16816(acc[0][0], src[0][s], r0, r1);
        mma16816(acc[1][0], src[1][s], r0, r1);
        mma16816(acc[0][1], src[0][s], r2, r3);
        mma16816(acc[1][1], src[1][s], r2, r3);
    }
#pragma unroll
    for (int mt = 0; mt < 2; mt++) {
        dst[mt][p][0] = relu_pack(acc[mt][0][0], acc[mt][0][1]);
        dst[mt][p][1] = relu_pack(acc[mt][0][2], acc[mt][0][3]);
        dst[mt][p][2] = relu_pack(acc[mt][1][0], acc[mt][1][1]);
        dst[mt][p][3] = relu_pack(acc[mt][1][2], acc[mt][1][3]);
    }
}

__global__ __launch_bounds__(THREADS, 1)
void FullyFusedMLP_kernel(
    const float* __restrict__ x,
    const float* __restrict__ w_in,  const float* __restrict__ b_in,
    const float* __restrict__ w_hid, const float* __restrict__ b_hid,
    const float* __restrict__ w_out, const float* __restrict__ b_out,
    float* __restrict__ out)
{
    extern __shared__ char smem_raw[];
    half* sh = (half*)smem_raw;
    half* w0 = sh + OFF_W0;
    half* w1 = sh + OFF_W1;
    half* w2 = sh + OFF_W2;
    half* w3 = sh + OFF_W3;
    half* w4 = sh + OFF_W4;
    float* biass = (float*)(smem_raw + BIAS_OFF);
    // bias layout: [0:128) b_in, [128:512) b_hid (3x128), [512:576) b_out

    const int tid = threadIdx.x;

    // ---- stage weights/biases to shared once per CTA ----
    for (int i = tid; i < 128 * 64; i += THREADS) {
        int n = i >> 6, k = i & 63;
        w0[n * SW0 + k] = __float2half(w_in[i]);
    }
    {
        half* wl[3] = {w1, w2, w3};
#pragma unroll
        for (int l = 0; l < 3; l++) {
            const float* src = w_hid + l * 128 * 128;
            half* dst = wl[l];
            for (int i = tid; i < 128 * 128; i += THREADS) {
                int n = i >> 7, k = i & 127;
                dst[n * SA + k] = __float2half(src[i]);
            }
        }
    }
    for (int i = tid; i < 64 * 128; i += THREADS) {
        int n = i >> 7, k = i & 127;
        w4[n * SA + k] = __float2half(w_out[i]);
    }
    for (int i = tid; i < 128; i += THREADS)     biass[i]       = b_in[i];
    for (int i = tid; i < 3 * 128; i += THREADS) biass[128 + i] = b_hid[i];
    for (int i = tid; i < 64; i += THREADS)      biass[512 + i] = b_out[i];
    __syncthreads();   // the ONLY sync

    const int warp = tid >> 5, lane = tid & 31;
    const int g = lane >> 2, t = lane & 3;

    // per-lane LDSM base offsets (halves): group=lane>>3 selects the fragment:
    //   n-offset = (group>>1)*8 + (lane&7), k-offset = (group&1)*8
    const int nofs = ((lane >> 4) * 8) + (lane & 7);
    const int kofs = ((lane >> 3) & 1) * 8;
    const uint32_t base_sa  = (uint32_t)(nofs * SA  + kofs) * 2u;
    const uint32_t base_sw0 = (uint32_t)(nofs * SW0 + kofs) * 2u;

    const uint32_t wb0 = smem_u32(w0) + base_sw0;
    const uint32_t wb1 = smem_u32(w1) + base_sa;
    const uint32_t wb2 = smem_u32(w2) + base_sa;
    const uint32_t wb3 = smem_u32(w3) + base_sa;
    const uint32_t wb4 = smem_u32(w4) + base_sa;

    uint32_t af[2][8][4];    // ping
    uint32_t bf[2][8][4];    // pong

    const int gwarp   = blockIdx.x * WARPS + warp;
    const int wstride = gridDim.x * WARPS;

    for (int wt = gwarp; wt < WTILES; wt += wstride) {
        const size_t row0 = (size_t)wt * M_PER_WARP;

        // ---- x: gmem -> af A-frags (fp32 -> fp16), k-blocks 0..3 ----
        {
            const float* xp = x + row0 * 64;
#pragma unroll
            for (int mt = 0; mt < 2; mt++) {
                const int rA = mt * 16 + g;
#pragma unroll
                for (int s = 0; s < 4; s++) {
                    const int c0 = s * 16 + t * 2;
                    float2 v0 = *(const float2*)&xp[rA * 64 + c0];
                    float2 v1 = *(const float2*)&xp[(rA + 8) * 64 + c0];
                    float2 v2 = *(const float2*)&xp[rA * 64 + c0 + 8];
                    float2 v3 = *(const float2*)&xp[(rA + 8) * 64 + c0 + 8];
                    af[mt][s][0] = packh2(v0.x, v0.y);
                    af[mt][s][1] = packh2(v1.x, v1.y);
                    af[mt][s][2] = packh2(v2.x, v2.y);
                    af[mt][s][3] = packh2(v3.x, v3.y);
                }
            }
        }

        // ---- layer 0: K=64, af -> bf ----
#pragma unroll
        for (int p = 0; p < 8; p++)
            layer_pair<4>(wb0, SW0, biass, af, bf, p, t);

        // ---- layer 1: K=128, bf -> af ----
#pragma unroll
        for (int p = 0; p < 8; p++)
            layer_pair<8>(wb1, SA, biass + 128, bf, af, p, t);

        // ---- layer 2: af -> bf ----
#pragma unroll
        for (int p = 0; p < 8; p++)
            layer_pair<8>(wb2, SA, biass + 256, af, bf, p, t);

        // ---- layer 3: bf -> af ----
#pragma unroll
        for (int p = 0; p < 8; p++)
            layer_pair<8>(wb3, SA, biass + 384, bf, af, p, t);

        // ---- layer 4: K=128 -> N=64, no activation, store fp32 ----
        const float* bo = biass + 512;
#pragma unroll
        for (int p = 0; p < 4; p++) {
            float acc[2][2][4];
#pragma unroll
            for (int jj = 0; jj < 2; jj++) {
                const float2 bb = *(const float2*)&bo[(p * 2 + jj) * 8 + t * 2];
#pragma unroll
                for (int mt = 0; mt < 2; mt++) {
                    acc[mt][jj][0] = bb.x; acc[mt][jj][1] = bb.y;
                    acc[mt][jj][2] = bb.x; acc[mt][jj][3] = bb.y;
                }
            }
            const uint32_t pbase = wb4 + (uint32_t)(p * 16 * SA) * 2u;
#pragma unroll
            for (int s = 0; s < 8; s++) {
                uint32_t r0, r1, r2, r3;
                ldsm4(r0, r1, r2, r3, pbase + (uint32_t)(s * 32));
                mma16816(acc[0][0], af[0][s], r0, r1);
                mma16816(acc[1][0], af[1][s], r0, r1);
                mma16816(acc[0][1], af[0][s], r2, r3);
                mma16816(acc[1][1], af[1][s], r2, r3);
            }
#pragma unroll
            for (int mt = 0; mt < 2; mt++) {
                const size_t r = row0 + mt * 16 + g;
#pragma unroll
                for (int jj = 0; jj < 2; jj++) {
                    const int n = (p * 2 + jj) * 8 + t * 2;
                    *(float2*)&out[r * 64 + n]       = make_float2(acc[mt][jj][0], acc[mt][jj][1]);
                    *(float2*)&out[(r + 8) * 64 + n] = make_float2(acc[mt][jj][2], acc[mt][jj][3]);
                }
            }
        }
    }
}

extern "C" void kernel_launch(void* const* d_in, const int* in_sizes, int n_in,
                              void* d_out, int out_size) {
    const float* x     = (const float*)d_in[0];
    const float* w_in  = (const float*)d_in[1];
    const float* b_in  = (const float*)d_in[2];
    const float* w_hid = (const float*)d_in[3];
    const float* b_hid = (const float*)d_in[4];
    const float* w_out = (const float*)d_in[5];
    const float* b_out = (const float*)d_in[6];
    float* out = (float*)d_out;

    int nsm = 148;
    cudaDeviceGetAttribute(&nsm, cudaDevAttrMultiProcessorCount, 0);
    if (nsm < 1) nsm = 148;
    int grid = nsm;

    cudaFuncSetAttribute(FullyFusedMLP_kernel,
                         cudaFuncAttributeMaxDynamicSharedMemorySize, SMEM_BYTES);
    FullyFusedMLP_kernel<<<grid, THREADS, SMEM_BYTES>>>(
        x, w_in, b_in, w_hid, b_hid, w_out, b_out, out);
}